// round 12
// baseline (speedup 1.0000x reference)
#include <cuda_runtime.h>
#include <cuda_bf16.h>

// EISANI sparse ternary net. B=512, F=128, NUM_BITS=16, E=2048, H=8192, C=10.
// R11 = R9 skeleton (persistent sweeps, fork/join, HS layers, pads) with the
// extraction inner loop rewritten: 64B (16 floats, one row) per thread-step,
// OR-reduce zero skip (~5 LOP3 per 64B common path), one atomic per sign per
// 16-group. Encode = R10 64-block version.

#define HID 8192
#define ENC 2048
#define BATCH 512
#define NGRP 16
#define CAP 96
#define CLASSES 10
#define OCH 128
#define NCHUNK (3 * HID / OCH)      // 192

// entry slot j of row h lives at u16 address ((j>>1)*2*HID + 2*h + (j&1));
// u32 view index (j>>1)*HID + h holds entries j (lo) and j+1 (hi).
#define ESLOT(j, h) ((((j) >> 1) * 2 * HID) + 2 * (h) + ((j) & 1))

// ---------------- scratch ----------------
__device__ unsigned short g_ent0[CAP * HID];
__device__ unsigned short g_ent1[CAP * HID];
__device__ unsigned short g_ent2[CAP * HID];
__device__ int g_cnt[6 * HID];      // pc0,nc0,pc1,nc1,pc2,nc2 (zeroed by outfinal)
__device__ int g_cp0[HID], g_ns0[HID];
__device__ int g_cp1[HID], g_ns1[HID];
__device__ int g_cp2[HID], g_ns2[HID];
__device__ unsigned g_act0[NGRP * ENC];
__device__ unsigned g_act1[NGRP * HID];
__device__ unsigned g_act2[NGRP * HID];
__device__ unsigned g_act3[NGRP * HID];
__device__ float    g_part[NCHUNK * BATCH * CLASSES];
__device__ float    g_sink[BATCH * CLASSES + BATCH];

// ---------------- 1) extraction: 64B/thread-step, OR-skip ----------------
__global__ __launch_bounds__(256) void extract_kernel(
    const float4* __restrict__ W, int f4shf, int total_f4,
    unsigned short* __restrict__ entT, int* __restrict__ pc, int* __restrict__ nc)
{
    int t  = blockIdx.x * blockDim.x + threadIdx.x;
    int NT = gridDim.x * blockDim.x;
    int f4mask = (1 << f4shf) - 1;

    #pragma unroll 1
    for (int base4 = t * 4; base4 < total_f4; base4 += NT * 4) {
        float4 v0 = __ldcs(W + base4 + 0);
        float4 v1 = __ldcs(W + base4 + 1);
        float4 v2 = __ldcs(W + base4 + 2);
        float4 v3 = __ldcs(W + base4 + 3);

        unsigned m =
            (__float_as_uint(v0.x) | __float_as_uint(v0.y) |
             __float_as_uint(v0.z) | __float_as_uint(v0.w) |
             __float_as_uint(v1.x) | __float_as_uint(v1.y) |
             __float_as_uint(v1.z) | __float_as_uint(v1.w) |
             __float_as_uint(v2.x) | __float_as_uint(v2.y) |
             __float_as_uint(v2.z) | __float_as_uint(v2.w) |
             __float_as_uint(v3.x) | __float_as_uint(v3.y) |
             __float_as_uint(v3.z) | __float_as_uint(v3.w)) << 1;
        if (m == 0u) continue;          // all 16 exactly +/-0

        float ff[16] = {v0.x, v0.y, v0.z, v0.w, v1.x, v1.y, v1.z, v1.w,
                        v2.x, v2.y, v2.z, v2.w, v3.x, v3.y, v3.z, v3.w};
        int cntp = 0, cntn = 0;
        #pragma unroll
        for (int k = 0; k < 16; k++) {
            cntp += (ff[k] > 0.f);
            cntn += (ff[k] < 0.f);
        }
        int row  = base4 >> f4shf;
        int col0 = (base4 & f4mask) << 2;
        if (cntp) {
            int bp = atomicAdd(&pc[row], cntp);
            #pragma unroll
            for (int k = 0; k < 16; k++) {
                if (ff[k] > 0.f) {
                    if (bp < CAP) entT[ESLOT(bp, row)] = (unsigned short)(col0 + k);
                    bp++;
                }
            }
        }
        if (cntn) {
            int bn = atomicAdd(&nc[row], cntn);
            #pragma unroll
            for (int k = 0; k < 16; k++) {
                if (ff[k] < 0.f) {
                    int sl = CAP - 1 - bn;
                    if (sl >= 0) entT[ESLOT(sl, row)] = (unsigned short)(col0 + k);
                    bn++;
                }
            }
        }
    }
}

// ---------------- pad: round counts to mult of 8 with sentinels -------------
__device__ __forceinline__ void pad_row(int row, const int* pc, const int* nc,
                                        int P, unsigned short* entT,
                                        int* cp8, int* ns8)
{
    int cp = min(pc[row], 48);
    int cn = min(nc[row], 48);
    int cpp = (cp + 7) & ~7;
    for (int j = cp; j < cpp; j++) entT[ESLOT(j, row)] = (unsigned short)P;
    int ns  = CAP - cn;
    int nsp = ns & ~7;
    for (int j = nsp; j < ns; j++) entT[ESLOT(j, row)] = (unsigned short)P;
    cp8[row] = cpp;
    ns8[row] = nsp;
}

__global__ void pad_kernel(const int* __restrict__ pc, const int* __restrict__ nc,
                           int P, unsigned short* __restrict__ entT,
                           int* __restrict__ cp8, int* __restrict__ ns8)
{
    int row = blockIdx.x * blockDim.x + threadIdx.x;
    if (row < HID) pad_row(row, pc, nc, P, entT, cp8, ns8);
}

__global__ void pad2_kernel(
    const int* __restrict__ pcA, const int* __restrict__ ncA,
    unsigned short* __restrict__ eA, int* __restrict__ cpA, int* __restrict__ nsA,
    const int* __restrict__ pcB, const int* __restrict__ ncB,
    unsigned short* __restrict__ eB, int* __restrict__ cpB, int* __restrict__ nsB)
{
    int row = blockIdx.x * blockDim.x + threadIdx.x;
    if (row >= HID) return;
    if (blockIdx.y == 0) pad_row(row, pcA, ncA, HID, eA, cpA, nsA);
    else                 pad_row(row, pcB, ncB, HID, eB, cpB, nsB);
}

// ---------------- 2) thermometer encode (64 blocks) ----------------
__global__ __launch_bounds__(256) void encode_kernel(
    const float* __restrict__ x, unsigned* __restrict__ act0T)
{
    __shared__ float xs[32][33];
    int g  = blockIdx.x;       // batch group
    int fq = blockIdx.y;       // feature quarter
    int tid = threadIdx.x;
    for (int k = tid; k < 1024; k += 256) {
        int b = k >> 5, f = k & 31;
        xs[b][f] = x[(size_t)(g * 32 + b) * 128 + fq * 32 + f];
    }
    __syncthreads();
    int w = tid >> 5, lane = tid & 31;
    #pragma unroll
    for (int ff = 0; ff < 4; ff++) {
        int f = w * 4 + ff;
        float xv = xs[lane][f] * 16.0f;
        unsigned myword = 0;
        #pragma unroll
        for (int j = 0; j < 16; j++) {
            unsigned m = __ballot_sync(0xFFFFFFFFu, xv > (float)j);
            if (lane == j) myword = m;
        }
        if (lane < 16) act0T[g * ENC + (fq * 32 + f) * 16 + lane] = myword;
    }
}

// ---------------- 3) bit-sliced layer (Harley-Seal, R9 exact) ---------------
__device__ __forceinline__ void csa(unsigned& c, unsigned& s, unsigned a, unsigned b)
{
    unsigned t = s ^ a;
    c = (s & a) | (t & b);
    s = t ^ b;
}

__device__ __forceinline__ void hs8(unsigned (&pl)[6],
    unsigned v0, unsigned v1, unsigned v2, unsigned v3,
    unsigned v4, unsigned v5, unsigned v6, unsigned v7)
{
    unsigned a1, a2, a3, a4, b1, b2, c1;
    csa(a1, pl[0], v0, v1);
    csa(a2, pl[0], v2, v3);
    csa(a3, pl[0], v4, v5);
    csa(a4, pl[0], v6, v7);
    csa(b1, pl[1], a1, a2);
    csa(b2, pl[1], a3, a4);
    csa(c1, pl[2], b1, b2);
    unsigned t0 = pl[3] & c1; pl[3] ^= c1;
    unsigned t1 = pl[4] & t0; pl[4] ^= t0;
    pl[5] ^= t1;
}

template <int KDIM>
__global__ __launch_bounds__(256) void layer_kernel(
    const unsigned* __restrict__ entP,      // paired u32 view
    const int* __restrict__ cp8, const int* __restrict__ ns8,
    const unsigned* __restrict__ actInT,
    unsigned* __restrict__ actOutT)
{
    __shared__ unsigned slice[KDIM + 4];
    int tid = threadIdx.x;
    int h = blockIdx.x * 256 + tid;
    int g = blockIdx.y;
    const uint4* src4 = reinterpret_cast<const uint4*>(actInT + (size_t)g * KDIM);
    uint4* dst4 = reinterpret_cast<uint4*>(slice);
    for (int i = tid; i < KDIM / 4; i += 256) dst4[i] = src4[i];
    if (tid == 0) slice[KDIM] = 0u;    // sentinel for padded entries
    __syncthreads();

    int cp = cp8[h];
    int ns = ns8[h];
    unsigned p[6] = {0, 0, 0, 0, 0, 0};
    unsigned n[6] = {0, 0, 0, 0, 0, 0};
    const unsigned* ep = entP + h;

    #pragma unroll 1
    for (int j = 0; j < cp; j += 8) {
        int jj = j >> 1;
        unsigned e0 = ep[(jj + 0) * HID], e1 = ep[(jj + 1) * HID];
        unsigned e2 = ep[(jj + 2) * HID], e3 = ep[(jj + 3) * HID];
        hs8(p, slice[e0 & 0xFFFF], slice[e0 >> 16],
               slice[e1 & 0xFFFF], slice[e1 >> 16],
               slice[e2 & 0xFFFF], slice[e2 >> 16],
               slice[e3 & 0xFFFF], slice[e3 >> 16]);
    }
    #pragma unroll 1
    for (int j = ns; j < CAP; j += 8) {
        int jj = j >> 1;
        unsigned e0 = ep[(jj + 0) * HID], e1 = ep[(jj + 1) * HID];
        unsigned e2 = ep[(jj + 2) * HID], e3 = ep[(jj + 3) * HID];
        hs8(n, slice[e0 & 0xFFFF], slice[e0 >> 16],
               slice[e1 & 0xFFFF], slice[e1 >> 16],
               slice[e2 & 0xFFFF], slice[e2 >> 16],
               slice[e3 & 0xFFFF], slice[e3 >> 16]);
    }

    // S = P + ~N (6-bit); z = P - N >= 4 <=> S >= 67 (1000011b)
    unsigned s[7], carry = 0;
    #pragma unroll
    for (int i = 0; i < 6; i++) {
        unsigned q = ~n[i];
        unsigned x1 = p[i] ^ q;
        s[i] = x1 ^ carry;
        carry = (p[i] & q) | (carry & x1);
    }
    s[6] = carry;
    unsigned gt = 0, eq = 0xFFFFFFFFu;
    eq &= s[6];
    #pragma unroll
    for (int i = 5; i >= 2; i--) { gt |= eq & s[i]; eq &= ~s[i]; }
    eq &= s[1];
    eq &= s[0];
    actOutT[(size_t)g * HID + h] = gt | eq;
}

// ---------------- 4a) output partials (R9 fused 3-layer form) ---------------
__global__ __launch_bounds__(256) void outpart_kernel(
    const unsigned* __restrict__ a1, const unsigned* __restrict__ a2,
    const unsigned* __restrict__ a3, const float* __restrict__ outConn,
    float* __restrict__ part)
{
    __shared__ float    ocs[OCH * CLASSES];
    __shared__ unsigned ws[OCH * 8];
    int chunk = blockIdx.x;
    int half  = blockIdx.y;
    int layer = chunk >> 6;
    int hbase = (chunk & 63) * OCH;
    const unsigned* act = (layer == 0) ? a1 : (layer == 1) ? a2 : a3;
    const float* oc = outConn + ((size_t)layer * HID + hbase) * CLASSES;
    int tid = threadIdx.x;
    for (int i = tid; i < OCH * CLASSES; i += 256) ocs[i] = oc[i];
    for (int i = tid; i < OCH * 8; i += 256) {
        int hh = i >> 3, gl = i & 7;
        ws[i] = act[(size_t)(half * 8 + gl) * HID + hbase + hh];
    }
    __syncthreads();

    int gl = tid >> 5, lane = tid & 31;
    int b = half * 256 + tid;
    unsigned long long acc[5] = {0ull, 0ull, 0ull, 0ull, 0ull};

    #pragma unroll 4
    for (int hh = 0; hh < OCH; hh++) {
        unsigned w = ws[hh * 8 + gl];
        unsigned bfbits = ((w >> lane) & 1u) ? 0x3f800000u : 0u;
        unsigned long long bfp = (unsigned long long)bfbits |
                                 ((unsigned long long)bfbits << 32);
        const unsigned long long* ocp =
            reinterpret_cast<const unsigned long long*>(&ocs[hh * CLASSES]);
        #pragma unroll
        for (int i = 0; i < 5; i++) {
            unsigned long long o = ocp[i];
            asm("fma.rn.f32x2 %0, %1, %2, %0;" : "+l"(acc[i]) : "l"(bfp), "l"(o));
        }
    }
    float* dst = part + ((size_t)chunk * BATCH + b) * CLASSES;
    #pragma unroll
    for (int i = 0; i < 5; i++) {
        dst[2 * i + 0] = __uint_as_float((unsigned)(acc[i] & 0xFFFFFFFFull));
        dst[2 * i + 1] = __uint_as_float((unsigned)(acc[i] >> 32));
    }
}

// ---------------- 4b) reduce + argmax + zero counts ----------------
__global__ __launch_bounds__(320) void outfinal_kernel(
    const float* __restrict__ part, float* __restrict__ preds_out,
    float* __restrict__ outact_out, int* __restrict__ cnt)
{
    int b = blockIdx.x;
    int t = threadIdx.x;                // 10 warps, one per class
    if (t < 96) cnt[b * 96 + t] = 0;    // 512*96 = 6*HID
    int w = t >> 5, l = t & 31;
    __shared__ float fin[CLASSES];
    float s = 0.f;
    #pragma unroll
    for (int i = 0; i < 6; i++) {
        int ch = l + i * 32;
        s += part[((size_t)ch * BATCH + b) * CLASSES + w];
    }
    #pragma unroll
    for (int off = 16; off > 0; off >>= 1)
        s += __shfl_down_sync(0xFFFFFFFFu, s, off);
    if (l == 0) {
        fin[w] = s;
        outact_out[b * CLASSES + w] = s;
    }
    __syncthreads();
    if (t == 0) {
        int bi = 0;
        float bv = fin[0];
        #pragma unroll
        for (int c = 1; c < CLASSES; c++)
            if (fin[c] > bv) { bv = fin[c]; bi = c; }
        preds_out[b] = (float)bi;
    }
}

// ---------------- host (exact R9 schedule) ----------------
static cudaStream_t s_side = nullptr;
static cudaEvent_t  s_evFork = nullptr, s_evJoin = nullptr;

extern "C" void kernel_launch(void* const* d_in, const int* in_sizes, int n_in,
                              void* d_out, int out_size)
{
    const float* x       = (const float*)d_in[1];
    const float* W0      = (const float*)d_in[2];
    const float* W1      = (const float*)d_in[3];
    const float* W2      = (const float*)d_in[4];
    const float* outConn = (const float*)d_in[5];

    if (!s_side) {
        cudaStreamCreateWithFlags(&s_side, cudaStreamNonBlocking);
        cudaEventCreateWithFlags(&s_evFork, cudaEventDisableTiming);
        cudaEventCreateWithFlags(&s_evJoin, cudaEventDisableTiming);
    }

    void *ent0, *ent1, *ent2, *cnt;
    void *cp0, *ns0, *cp1, *ns1, *cp2, *ns2;
    void *act0, *act1, *act2, *act3, *part, *sink;
    cudaGetSymbolAddress(&ent0, g_ent0);  cudaGetSymbolAddress(&ent1, g_ent1);
    cudaGetSymbolAddress(&ent2, g_ent2);  cudaGetSymbolAddress(&cnt,  g_cnt);
    cudaGetSymbolAddress(&cp0, g_cp0);    cudaGetSymbolAddress(&ns0, g_ns0);
    cudaGetSymbolAddress(&cp1, g_cp1);    cudaGetSymbolAddress(&ns1, g_ns1);
    cudaGetSymbolAddress(&cp2, g_cp2);    cudaGetSymbolAddress(&ns2, g_ns2);
    cudaGetSymbolAddress(&act0, g_act0);  cudaGetSymbolAddress(&act1, g_act1);
    cudaGetSymbolAddress(&act2, g_act2);  cudaGetSymbolAddress(&act3, g_act3);
    cudaGetSymbolAddress(&part, g_part);  cudaGetSymbolAddress(&sink, g_sink);

    int* pc0 = (int*)cnt;          int* nc0 = pc0 + HID;
    int* pc1 = nc0 + HID;          int* nc1 = pc1 + HID;
    int* pc2 = nc1 + HID;          int* nc2 = pc2 + HID;

    float* preds_dst;
    float* outact_dst;
    if (out_size == BATCH * CLASSES + BATCH) {
        preds_dst  = (float*)d_out;
        outact_dst = (float*)d_out + BATCH;
    } else if (out_size == BATCH * CLASSES) {
        preds_dst  = (float*)sink;
        outact_dst = (float*)d_out;
    } else if (out_size == BATCH) {
        preds_dst  = (float*)d_out;
        outact_dst = (float*)sink;
    } else {
        preds_dst  = (float*)d_out;
        outact_dst = (float*)d_out + BATCH;
    }

    const int XGRID = 1184;
    dim3 lgrid(HID / 256, NGRP);
    dim3 egrid(NGRP, 4);

    // ---- fork side chain ----
    cudaEventRecord(s_evFork, 0);
    cudaStreamWaitEvent(s_side, s_evFork, 0);

    encode_kernel<<<egrid, 256, 0, s_side>>>(x, (unsigned*)act0);
    extract_kernel<<<XGRID, 256, 0, s_side>>>((const float4*)W0, 9, HID * (ENC / 4),
                                              (unsigned short*)ent0, pc0, nc0);
    pad_kernel<<<HID / 256, 256, 0, s_side>>>(pc0, nc0, ENC, (unsigned short*)ent0,
                                              (int*)cp0, (int*)ns0);
    layer_kernel<ENC><<<lgrid, 256, 0, s_side>>>((unsigned*)ent0, (int*)cp0,
                                                 (int*)ns0, (unsigned*)act0,
                                                 (unsigned*)act1);
    cudaEventRecord(s_evJoin, s_side);

    // ---- main chain: the two big HBM sweeps ----
    extract_kernel<<<XGRID, 256>>>((const float4*)W1, 11, HID * (HID / 4),
                                   (unsigned short*)ent1, pc1, nc1);
    extract_kernel<<<XGRID, 256>>>((const float4*)W2, 11, HID * (HID / 4),
                                   (unsigned short*)ent2, pc2, nc2);
    dim3 pgrid(HID / 256, 2);
    pad2_kernel<<<pgrid, 256>>>(pc1, nc1, (unsigned short*)ent1, (int*)cp1, (int*)ns1,
                                pc2, nc2, (unsigned short*)ent2, (int*)cp2, (int*)ns2);

    cudaStreamWaitEvent(0, s_evJoin, 0);

    layer_kernel<HID><<<lgrid, 256>>>((unsigned*)ent1, (int*)cp1, (int*)ns1,
                                      (unsigned*)act1, (unsigned*)act2);
    layer_kernel<HID><<<lgrid, 256>>>((unsigned*)ent2, (int*)cp2, (int*)ns2,
                                      (unsigned*)act2, (unsigned*)act3);

    dim3 ogrid(NCHUNK, 2);
    outpart_kernel<<<ogrid, 256>>>((unsigned*)act1, (unsigned*)act2, (unsigned*)act3,
                                   outConn, (float*)part);
    outfinal_kernel<<<BATCH, 320>>>((float*)part, preds_dst, outact_dst, (int*)cnt);
}

// round 13
// speedup vs baseline: 1.0010x; 1.0010x over previous
#include <cuda_runtime.h>
#include <cuda_bf16.h>

// EISANI sparse ternary net. B=512, F=128, NUM_BITS=16, E=2048, H=8192, C=10.
// R11 = R9 skeleton (persistent sweeps, fork/join, HS layers, pads) with the
// extraction inner loop rewritten: 64B (16 floats, one row) per thread-step,
// OR-reduce zero skip (~5 LOP3 per 64B common path), one atomic per sign per
// 16-group. Encode = R10 64-block version.

#define HID 8192
#define ENC 2048
#define BATCH 512
#define NGRP 16
#define CAP 96
#define CLASSES 10
#define OCH 128
#define NCHUNK (3 * HID / OCH)      // 192

// entry slot j of row h lives at u16 address ((j>>1)*2*HID + 2*h + (j&1));
// u32 view index (j>>1)*HID + h holds entries j (lo) and j+1 (hi).
#define ESLOT(j, h) ((((j) >> 1) * 2 * HID) + 2 * (h) + ((j) & 1))

// ---------------- scratch ----------------
__device__ unsigned short g_ent0[CAP * HID];
__device__ unsigned short g_ent1[CAP * HID];
__device__ unsigned short g_ent2[CAP * HID];
__device__ int g_cnt[6 * HID];      // pc0,nc0,pc1,nc1,pc2,nc2 (zeroed by outfinal)
__device__ int g_cp0[HID], g_ns0[HID];
__device__ int g_cp1[HID], g_ns1[HID];
__device__ int g_cp2[HID], g_ns2[HID];
__device__ unsigned g_act0[NGRP * ENC];
__device__ unsigned g_act1[NGRP * HID];
__device__ unsigned g_act2[NGRP * HID];
__device__ unsigned g_act3[NGRP * HID];
__device__ float    g_part[NCHUNK * BATCH * CLASSES];
__device__ float    g_sink[BATCH * CLASSES + BATCH];

// ---------------- 1) extraction: 64B/thread-step, OR-skip ----------------
__global__ __launch_bounds__(256) void extract_kernel(
    const float4* __restrict__ W, int f4shf, int total_f4,
    unsigned short* __restrict__ entT, int* __restrict__ pc, int* __restrict__ nc)
{
    int t  = blockIdx.x * blockDim.x + threadIdx.x;
    int NT = gridDim.x * blockDim.x;
    int f4mask = (1 << f4shf) - 1;

    #pragma unroll 1
    for (int base4 = t * 4; base4 < total_f4; base4 += NT * 4) {
        float4 v0 = __ldcs(W + base4 + 0);
        float4 v1 = __ldcs(W + base4 + 1);
        float4 v2 = __ldcs(W + base4 + 2);
        float4 v3 = __ldcs(W + base4 + 3);

        unsigned m =
            (__float_as_uint(v0.x) | __float_as_uint(v0.y) |
             __float_as_uint(v0.z) | __float_as_uint(v0.w) |
             __float_as_uint(v1.x) | __float_as_uint(v1.y) |
             __float_as_uint(v1.z) | __float_as_uint(v1.w) |
             __float_as_uint(v2.x) | __float_as_uint(v2.y) |
             __float_as_uint(v2.z) | __float_as_uint(v2.w) |
             __float_as_uint(v3.x) | __float_as_uint(v3.y) |
             __float_as_uint(v3.z) | __float_as_uint(v3.w)) << 1;
        if (m == 0u) continue;          // all 16 exactly +/-0

        float ff[16] = {v0.x, v0.y, v0.z, v0.w, v1.x, v1.y, v1.z, v1.w,
                        v2.x, v2.y, v2.z, v2.w, v3.x, v3.y, v3.z, v3.w};
        int cntp = 0, cntn = 0;
        #pragma unroll
        for (int k = 0; k < 16; k++) {
            cntp += (ff[k] > 0.f);
            cntn += (ff[k] < 0.f);
        }
        int row  = base4 >> f4shf;
        int col0 = (base4 & f4mask) << 2;
        if (cntp) {
            int bp = atomicAdd(&pc[row], cntp);
            #pragma unroll
            for (int k = 0; k < 16; k++) {
                if (ff[k] > 0.f) {
                    if (bp < CAP) entT[ESLOT(bp, row)] = (unsigned short)(col0 + k);
                    bp++;
                }
            }
        }
        if (cntn) {
            int bn = atomicAdd(&nc[row], cntn);
            #pragma unroll
            for (int k = 0; k < 16; k++) {
                if (ff[k] < 0.f) {
                    int sl = CAP - 1 - bn;
                    if (sl >= 0) entT[ESLOT(sl, row)] = (unsigned short)(col0 + k);
                    bn++;
                }
            }
        }
    }
}

// ---------------- pad: round counts to mult of 8 with sentinels -------------
__device__ __forceinline__ void pad_row(int row, const int* pc, const int* nc,
                                        int P, unsigned short* entT,
                                        int* cp8, int* ns8)
{
    int cp = min(pc[row], 48);
    int cn = min(nc[row], 48);
    int cpp = (cp + 7) & ~7;
    for (int j = cp; j < cpp; j++) entT[ESLOT(j, row)] = (unsigned short)P;
    int ns  = CAP - cn;
    int nsp = ns & ~7;
    for (int j = nsp; j < ns; j++) entT[ESLOT(j, row)] = (unsigned short)P;
    cp8[row] = cpp;
    ns8[row] = nsp;
}

__global__ void pad_kernel(const int* __restrict__ pc, const int* __restrict__ nc,
                           int P, unsigned short* __restrict__ entT,
                           int* __restrict__ cp8, int* __restrict__ ns8)
{
    int row = blockIdx.x * blockDim.x + threadIdx.x;
    if (row < HID) pad_row(row, pc, nc, P, entT, cp8, ns8);
}

__global__ void pad2_kernel(
    const int* __restrict__ pcA, const int* __restrict__ ncA,
    unsigned short* __restrict__ eA, int* __restrict__ cpA, int* __restrict__ nsA,
    const int* __restrict__ pcB, const int* __restrict__ ncB,
    unsigned short* __restrict__ eB, int* __restrict__ cpB, int* __restrict__ nsB)
{
    int row = blockIdx.x * blockDim.x + threadIdx.x;
    if (row >= HID) return;
    if (blockIdx.y == 0) pad_row(row, pcA, ncA, HID, eA, cpA, nsA);
    else                 pad_row(row, pcB, ncB, HID, eB, cpB, nsB);
}

// ---------------- 2) thermometer encode (64 blocks) ----------------
__global__ __launch_bounds__(256) void encode_kernel(
    const float* __restrict__ x, unsigned* __restrict__ act0T)
{
    __shared__ float xs[32][33];
    int g  = blockIdx.x;       // batch group
    int fq = blockIdx.y;       // feature quarter
    int tid = threadIdx.x;
    for (int k = tid; k < 1024; k += 256) {
        int b = k >> 5, f = k & 31;
        xs[b][f] = x[(size_t)(g * 32 + b) * 128 + fq * 32 + f];
    }
    __syncthreads();
    int w = tid >> 5, lane = tid & 31;
    #pragma unroll
    for (int ff = 0; ff < 4; ff++) {
        int f = w * 4 + ff;
        float xv = xs[lane][f] * 16.0f;
        unsigned myword = 0;
        #pragma unroll
        for (int j = 0; j < 16; j++) {
            unsigned m = __ballot_sync(0xFFFFFFFFu, xv > (float)j);
            if (lane == j) myword = m;
        }
        if (lane < 16) act0T[g * ENC + (fq * 32 + f) * 16 + lane] = myword;
    }
}

// ---------------- 3) bit-sliced layer (Harley-Seal, R9 exact) ---------------
__device__ __forceinline__ void csa(unsigned& c, unsigned& s, unsigned a, unsigned b)
{
    unsigned t = s ^ a;
    c = (s & a) | (t & b);
    s = t ^ b;
}

__device__ __forceinline__ void hs8(unsigned (&pl)[6],
    unsigned v0, unsigned v1, unsigned v2, unsigned v3,
    unsigned v4, unsigned v5, unsigned v6, unsigned v7)
{
    unsigned a1, a2, a3, a4, b1, b2, c1;
    csa(a1, pl[0], v0, v1);
    csa(a2, pl[0], v2, v3);
    csa(a3, pl[0], v4, v5);
    csa(a4, pl[0], v6, v7);
    csa(b1, pl[1], a1, a2);
    csa(b2, pl[1], a3, a4);
    csa(c1, pl[2], b1, b2);
    unsigned t0 = pl[3] & c1; pl[3] ^= c1;
    unsigned t1 = pl[4] & t0; pl[4] ^= t0;
    pl[5] ^= t1;
}

template <int KDIM>
__global__ __launch_bounds__(256) void layer_kernel(
    const unsigned* __restrict__ entP,      // paired u32 view
    const int* __restrict__ cp8, const int* __restrict__ ns8,
    const unsigned* __restrict__ actInT,
    unsigned* __restrict__ actOutT)
{
    __shared__ unsigned slice[KDIM + 4];
    int tid = threadIdx.x;
    int h = blockIdx.x * 256 + tid;
    int g = blockIdx.y;
    const uint4* src4 = reinterpret_cast<const uint4*>(actInT + (size_t)g * KDIM);
    uint4* dst4 = reinterpret_cast<uint4*>(slice);
    for (int i = tid; i < KDIM / 4; i += 256) dst4[i] = src4[i];
    if (tid == 0) slice[KDIM] = 0u;    // sentinel for padded entries
    __syncthreads();

    int cp = cp8[h];
    int ns = ns8[h];
    unsigned p[6] = {0, 0, 0, 0, 0, 0};
    unsigned n[6] = {0, 0, 0, 0, 0, 0};
    const unsigned* ep = entP + h;

    #pragma unroll 1
    for (int j = 0; j < cp; j += 8) {
        int jj = j >> 1;
        unsigned e0 = ep[(jj + 0) * HID], e1 = ep[(jj + 1) * HID];
        unsigned e2 = ep[(jj + 2) * HID], e3 = ep[(jj + 3) * HID];
        hs8(p, slice[e0 & 0xFFFF], slice[e0 >> 16],
               slice[e1 & 0xFFFF], slice[e1 >> 16],
               slice[e2 & 0xFFFF], slice[e2 >> 16],
               slice[e3 & 0xFFFF], slice[e3 >> 16]);
    }
    #pragma unroll 1
    for (int j = ns; j < CAP; j += 8) {
        int jj = j >> 1;
        unsigned e0 = ep[(jj + 0) * HID], e1 = ep[(jj + 1) * HID];
        unsigned e2 = ep[(jj + 2) * HID], e3 = ep[(jj + 3) * HID];
        hs8(n, slice[e0 & 0xFFFF], slice[e0 >> 16],
               slice[e1 & 0xFFFF], slice[e1 >> 16],
               slice[e2 & 0xFFFF], slice[e2 >> 16],
               slice[e3 & 0xFFFF], slice[e3 >> 16]);
    }

    // S = P + ~N (6-bit); z = P - N >= 4 <=> S >= 67 (1000011b)
    unsigned s[7], carry = 0;
    #pragma unroll
    for (int i = 0; i < 6; i++) {
        unsigned q = ~n[i];
        unsigned x1 = p[i] ^ q;
        s[i] = x1 ^ carry;
        carry = (p[i] & q) | (carry & x1);
    }
    s[6] = carry;
    unsigned gt = 0, eq = 0xFFFFFFFFu;
    eq &= s[6];
    #pragma unroll
    for (int i = 5; i >= 2; i--) { gt |= eq & s[i]; eq &= ~s[i]; }
    eq &= s[1];
    eq &= s[0];
    actOutT[(size_t)g * HID + h] = gt | eq;
}

// ---------------- 4a) output partials (R9 fused 3-layer form) ---------------
__global__ __launch_bounds__(256) void outpart_kernel(
    const unsigned* __restrict__ a1, const unsigned* __restrict__ a2,
    const unsigned* __restrict__ a3, const float* __restrict__ outConn,
    float* __restrict__ part)
{
    __shared__ float    ocs[OCH * CLASSES];
    __shared__ unsigned ws[OCH * 8];
    int chunk = blockIdx.x;
    int half  = blockIdx.y;
    int layer = chunk >> 6;
    int hbase = (chunk & 63) * OCH;
    const unsigned* act = (layer == 0) ? a1 : (layer == 1) ? a2 : a3;
    const float* oc = outConn + ((size_t)layer * HID + hbase) * CLASSES;
    int tid = threadIdx.x;
    for (int i = tid; i < OCH * CLASSES; i += 256) ocs[i] = oc[i];
    for (int i = tid; i < OCH * 8; i += 256) {
        int hh = i >> 3, gl = i & 7;
        ws[i] = act[(size_t)(half * 8 + gl) * HID + hbase + hh];
    }
    __syncthreads();

    int gl = tid >> 5, lane = tid & 31;
    int b = half * 256 + tid;
    unsigned long long acc[5] = {0ull, 0ull, 0ull, 0ull, 0ull};

    #pragma unroll 4
    for (int hh = 0; hh < OCH; hh++) {
        unsigned w = ws[hh * 8 + gl];
        unsigned bfbits = ((w >> lane) & 1u) ? 0x3f800000u : 0u;
        unsigned long long bfp = (unsigned long long)bfbits |
                                 ((unsigned long long)bfbits << 32);
        const unsigned long long* ocp =
            reinterpret_cast<const unsigned long long*>(&ocs[hh * CLASSES]);
        #pragma unroll
        for (int i = 0; i < 5; i++) {
            unsigned long long o = ocp[i];
            asm("fma.rn.f32x2 %0, %1, %2, %0;" : "+l"(acc[i]) : "l"(bfp), "l"(o));
        }
    }
    float* dst = part + ((size_t)chunk * BATCH + b) * CLASSES;
    #pragma unroll
    for (int i = 0; i < 5; i++) {
        dst[2 * i + 0] = __uint_as_float((unsigned)(acc[i] & 0xFFFFFFFFull));
        dst[2 * i + 1] = __uint_as_float((unsigned)(acc[i] >> 32));
    }
}

// ---------------- 4b) reduce + argmax + zero counts ----------------
__global__ __launch_bounds__(320) void outfinal_kernel(
    const float* __restrict__ part, float* __restrict__ preds_out,
    float* __restrict__ outact_out, int* __restrict__ cnt)
{
    int b = blockIdx.x;
    int t = threadIdx.x;                // 10 warps, one per class
    if (t < 96) cnt[b * 96 + t] = 0;    // 512*96 = 6*HID
    int w = t >> 5, l = t & 31;
    __shared__ float fin[CLASSES];
    float s = 0.f;
    #pragma unroll
    for (int i = 0; i < 6; i++) {
        int ch = l + i * 32;
        s += part[((size_t)ch * BATCH + b) * CLASSES + w];
    }
    #pragma unroll
    for (int off = 16; off > 0; off >>= 1)
        s += __shfl_down_sync(0xFFFFFFFFu, s, off);
    if (l == 0) {
        fin[w] = s;
        outact_out[b * CLASSES + w] = s;
    }
    __syncthreads();
    if (t == 0) {
        int bi = 0;
        float bv = fin[0];
        #pragma unroll
        for (int c = 1; c < CLASSES; c++)
            if (fin[c] > bv) { bv = fin[c]; bi = c; }
        preds_out[b] = (float)bi;
    }
}

// ---------------- host (exact R9 schedule) ----------------
static cudaStream_t s_side = nullptr;
static cudaEvent_t  s_evFork = nullptr, s_evJoin = nullptr;

extern "C" void kernel_launch(void* const* d_in, const int* in_sizes, int n_in,
                              void* d_out, int out_size)
{
    const float* x       = (const float*)d_in[1];
    const float* W0      = (const float*)d_in[2];
    const float* W1      = (const float*)d_in[3];
    const float* W2      = (const float*)d_in[4];
    const float* outConn = (const float*)d_in[5];

    if (!s_side) {
        cudaStreamCreateWithFlags(&s_side, cudaStreamNonBlocking);
        cudaEventCreateWithFlags(&s_evFork, cudaEventDisableTiming);
        cudaEventCreateWithFlags(&s_evJoin, cudaEventDisableTiming);
    }

    void *ent0, *ent1, *ent2, *cnt;
    void *cp0, *ns0, *cp1, *ns1, *cp2, *ns2;
    void *act0, *act1, *act2, *act3, *part, *sink;
    cudaGetSymbolAddress(&ent0, g_ent0);  cudaGetSymbolAddress(&ent1, g_ent1);
    cudaGetSymbolAddress(&ent2, g_ent2);  cudaGetSymbolAddress(&cnt,  g_cnt);
    cudaGetSymbolAddress(&cp0, g_cp0);    cudaGetSymbolAddress(&ns0, g_ns0);
    cudaGetSymbolAddress(&cp1, g_cp1);    cudaGetSymbolAddress(&ns1, g_ns1);
    cudaGetSymbolAddress(&cp2, g_cp2);    cudaGetSymbolAddress(&ns2, g_ns2);
    cudaGetSymbolAddress(&act0, g_act0);  cudaGetSymbolAddress(&act1, g_act1);
    cudaGetSymbolAddress(&act2, g_act2);  cudaGetSymbolAddress(&act3, g_act3);
    cudaGetSymbolAddress(&part, g_part);  cudaGetSymbolAddress(&sink, g_sink);

    int* pc0 = (int*)cnt;          int* nc0 = pc0 + HID;
    int* pc1 = nc0 + HID;          int* nc1 = pc1 + HID;
    int* pc2 = nc1 + HID;          int* nc2 = pc2 + HID;

    float* preds_dst;
    float* outact_dst;
    if (out_size == BATCH * CLASSES + BATCH) {
        preds_dst  = (float*)d_out;
        outact_dst = (float*)d_out + BATCH;
    } else if (out_size == BATCH * CLASSES) {
        preds_dst  = (float*)sink;
        outact_dst = (float*)d_out;
    } else if (out_size == BATCH) {
        preds_dst  = (float*)d_out;
        outact_dst = (float*)sink;
    } else {
        preds_dst  = (float*)d_out;
        outact_dst = (float*)d_out + BATCH;
    }

    const int XGRID = 1184;
    dim3 lgrid(HID / 256, NGRP);
    dim3 egrid(NGRP, 4);

    // ---- fork side chain ----
    cudaEventRecord(s_evFork, 0);
    cudaStreamWaitEvent(s_side, s_evFork, 0);

    encode_kernel<<<egrid, 256, 0, s_side>>>(x, (unsigned*)act0);
    extract_kernel<<<XGRID, 256, 0, s_side>>>((const float4*)W0, 9, HID * (ENC / 4),
                                              (unsigned short*)ent0, pc0, nc0);
    pad_kernel<<<HID / 256, 256, 0, s_side>>>(pc0, nc0, ENC, (unsigned short*)ent0,
                                              (int*)cp0, (int*)ns0);
    layer_kernel<ENC><<<lgrid, 256, 0, s_side>>>((unsigned*)ent0, (int*)cp0,
                                                 (int*)ns0, (unsigned*)act0,
                                                 (unsigned*)act1);
    cudaEventRecord(s_evJoin, s_side);

    // ---- main chain: the two big HBM sweeps ----
    extract_kernel<<<XGRID, 256>>>((const float4*)W1, 11, HID * (HID / 4),
                                   (unsigned short*)ent1, pc1, nc1);
    extract_kernel<<<XGRID, 256>>>((const float4*)W2, 11, HID * (HID / 4),
                                   (unsigned short*)ent2, pc2, nc2);
    dim3 pgrid(HID / 256, 2);
    pad2_kernel<<<pgrid, 256>>>(pc1, nc1, (unsigned short*)ent1, (int*)cp1, (int*)ns1,
                                pc2, nc2, (unsigned short*)ent2, (int*)cp2, (int*)ns2);

    cudaStreamWaitEvent(0, s_evJoin, 0);

    layer_kernel<HID><<<lgrid, 256>>>((unsigned*)ent1, (int*)cp1, (int*)ns1,
                                      (unsigned*)act1, (unsigned*)act2);
    layer_kernel<HID><<<lgrid, 256>>>((unsigned*)ent2, (int*)cp2, (int*)ns2,
                                      (unsigned*)act2, (unsigned*)act3);

    dim3 ogrid(NCHUNK, 2);
    outpart_kernel<<<ogrid, 256>>>((unsigned*)act1, (unsigned*)act2, (unsigned*)act3,
                                   outConn, (float*)part);
    outfinal_kernel<<<BATCH, 320>>>((float*)part, preds_dst, outact_dst, (int*)cnt);
}